// round 2
// baseline (speedup 1.0000x reference)
#include <cuda_runtime.h>
#include <cuda_bf16.h>
#include <cstdint>

#define B_   8
#define S_   512
#define D_   512
#define E_   128
#define VOC  32000
#define TS   32
#define KC   8
#define NCH  (E_ / KC)   // 16 chunks of 8 k-values

typedef unsigned long long u64;

// scratch: mT[b][i][o]  (2 MB), fully overwritten each call
__device__ float g_m[(size_t)B_ * E_ * D_];

// ---------------------------------------------------------------------------
// helpers: packed f32x2 FMA, pack/unpack, cp.async
// ---------------------------------------------------------------------------
__device__ __forceinline__ void ffma2(u64 &d, u64 a, u64 b) {
    asm("fma.rn.f32x2 %0, %1, %2, %0;" : "+l"(d) : "l"(a), "l"(b));
}
__device__ __forceinline__ u64 pack2(float x, float y) {
    u64 r; asm("mov.b64 %0, {%1, %2};" : "=l"(r) : "f"(x), "f"(y)); return r;
}
__device__ __forceinline__ float2 unpack2(u64 v) {
    float2 f; asm("mov.b64 {%0, %1}, %2;" : "=f"(f.x), "=f"(f.y) : "l"(v)); return f;
}
__device__ __forceinline__ void cp16(void* s, const void* g) {
    unsigned sa = (unsigned)__cvta_generic_to_shared(s);
    asm volatile("cp.async.cg.shared.global [%0], [%1], 16;" :: "r"(sa), "l"(g));
}
__device__ __forceinline__ void cp_commit() { asm volatile("cp.async.commit_group;"); }
template<int N> __device__ __forceinline__ void cp_wait() {
    asm volatile("cp.async.wait_group %0;" :: "n"(N));
}

// ---------------------------------------------------------------------------
// Kernel 1: mT[b][i][o] = sum_j W[o][i][j] * king_table[king_id[b]][j]
// One thread per (o,i): streams its 512B W row once, accumulates all 8 batches
// with f32x2 FMAs against broadcast smem king vectors. Stores coalesced in o.
// HBM-bound on W (33.5 MB).
// ---------------------------------------------------------------------------
__global__ __launch_bounds__(256) void k_proj(const float* __restrict__ W,
                                              const float* __restrict__ kt,
                                              const int*   __restrict__ kid) {
    __shared__ float sk[B_][E_];
    const int t = threadIdx.x;
    for (int idx = t; idx < B_ * E_; idx += 256) {
        int b = idx >> 7, j = idx & 127;
        sk[b][j] = kt[(size_t)kid[b] * E_ + j];
    }
    __syncthreads();

    const int gt = blockIdx.x * 256 + t;
    const int o = gt & 511;
    const int i = gt >> 9;
    const ulonglong2* Wr = (const ulonglong2*)(W + ((size_t)o * E_ + i) * E_);

    u64 acc[B_];
    #pragma unroll
    for (int b = 0; b < B_; ++b) acc[b] = 0ull;

    #pragma unroll 4
    for (int j4 = 0; j4 < 32; ++j4) {
        ulonglong2 w = Wr[j4];
        #pragma unroll
        for (int b = 0; b < B_; ++b) {
            ulonglong2 kv = *(const ulonglong2*)(&sk[b][j4 * 4]);
            ffma2(acc[b], w.x, kv.x);
            ffma2(acc[b], w.y, kv.y);
        }
    }
    #pragma unroll
    for (int b = 0; b < B_; ++b) {
        float2 f = unpack2(acc[b]);
        g_m[((size_t)b << 16) + ((size_t)i << 9) + o] = f.x + f.y;
    }
}

// ---------------------------------------------------------------------------
// Kernel 2: per (b, 32-seq tile): gather A = emb rows (32x128) into smem,
// x = A * mT[b] (128x512) with cp.async double-buffered M chunks, fused
// bias + LayerNorm. Microtile 8s x 8o per thread (o-quads at 4tq, 4tq+256).
// ---------------------------------------------------------------------------
__global__ __launch_bounds__(256) void k_main(const int*   __restrict__ seq,
                                              const int*   __restrict__ kid,
                                              const float* __restrict__ emb,
                                              const float* __restrict__ bias,
                                              const float* __restrict__ gamma,
                                              const float* __restrict__ beta,
                                              float*       __restrict__ out) {
    __shared__ __align__(16) unsigned char smem[49152];
    float* sA  = (float*)smem;                 // A[32][128]  (16 KB)
    float* sM0 = (float*)(smem + 16384);       // M chunk buf0 (16 KB)
    float* sM1 = (float*)(smem + 32768);       // M chunk buf1 (16 KB)
    float* red = (float*)(smem + 16384);       // LN reduction, reuses buf0

    const int t  = threadIdx.x;
    const int bb = blockIdx.y;
    const int s0 = blockIdx.x * TS;
    const int king = kid[bb];
    const float* Mg = g_m + ((size_t)bb << 16);   // mT[b] : [128][512]

    // group 0: A gather + M chunk 0 ; group 1: M chunk 1
    {
        const float* embk = emb + (size_t)king * VOC * E_;
        #pragma unroll
        for (int v = 0; v < 4; ++v) {
            int idx = t + v * 256;            // float4 index in [0,1024)
            int row = idx >> 5, c4 = idx & 31;
            int tok = seq[bb * S_ + s0 + row];
            cp16(sA + idx * 4, embk + (size_t)tok * E_ + c4 * 4);
        }
        #pragma unroll
        for (int v = 0; v < 4; ++v) {
            int idx = t + v * 256;
            cp16(sM0 + idx * 4, Mg + idx * 4);
        }
        cp_commit();
        #pragma unroll
        for (int v = 0; v < 4; ++v) {
            int idx = t + v * 256;
            cp16(sM1 + idx * 4, Mg + KC * D_ + idx * 4);
        }
        cp_commit();
    }

    const int tq = t & 63, tg = t >> 6;
    const int o0 = tq * 4, o1 = o0 + 256;

    u64 acc[8][4];
    #pragma unroll
    for (int s = 0; s < 8; ++s) {
        acc[s][0] = 0ull; acc[s][1] = 0ull; acc[s][2] = 0ull; acc[s][3] = 0ull;
    }

    const float* Arow = sA + tg * 8 * E_;

    #pragma unroll 1
    for (int c = 0; c < NCH; ++c) {
        if (c < NCH - 1) cp_wait<1>(); else cp_wait<0>();
        __syncthreads();
        const float* Mb = (c & 1) ? sM1 : sM0;
        #pragma unroll
        for (int k4 = 0; k4 < 2; ++k4) {
            float4 av[8];
            #pragma unroll
            for (int s = 0; s < 8; ++s)
                av[s] = *(const float4*)(Arow + s * E_ + c * KC + k4 * 4);
            #pragma unroll
            for (int kk = 0; kk < 4; ++kk) {
                const float* mrow = Mb + (k4 * 4 + kk) * D_;
                ulonglong2 m0 = *(const ulonglong2*)(mrow + o0);
                ulonglong2 m1 = *(const ulonglong2*)(mrow + o1);
                #pragma unroll
                for (int s = 0; s < 8; ++s) {
                    float a = (kk == 0) ? av[s].x : (kk == 1) ? av[s].y
                            : (kk == 2) ? av[s].z : av[s].w;
                    u64 aa = pack2(a, a);
                    ffma2(acc[s][0], aa, m0.x);
                    ffma2(acc[s][1], aa, m0.y);
                    ffma2(acc[s][2], aa, m1.x);
                    ffma2(acc[s][3], aa, m1.y);
                }
            }
        }
        __syncthreads();
        if (c + 2 < NCH) {
            float* dst = (c & 1) ? sM1 : sM0;   // buffer (c+2)&1 == c&1
            const float* src = Mg + (size_t)(c + 2) * KC * D_;
            #pragma unroll
            for (int v = 0; v < 4; ++v) {
                int idx = t + v * 256;
                cp16(dst + idx * 4, src + idx * 4);
            }
            cp_commit();
        }
    }

    // ---- epilogue: bias + LN stats ----
    const float4 b0 = *(const float4*)(bias + o0);
    const float4 b1 = *(const float4*)(bias + o1);
    float sum[8], ss[8];
    #pragma unroll
    for (int s = 0; s < 8; ++s) {
        float2 p0 = unpack2(acc[s][0]), p1 = unpack2(acc[s][1]);
        float2 p2 = unpack2(acc[s][2]), p3 = unpack2(acc[s][3]);
        float x0 = p0.x + b0.x, x1 = p0.y + b0.y, x2 = p1.x + b0.z, x3 = p1.y + b0.w;
        float x4 = p2.x + b1.x, x5 = p2.y + b1.y, x6 = p3.x + b1.z, x7 = p3.y + b1.w;
        acc[s][0] = pack2(x0, x1); acc[s][1] = pack2(x2, x3);
        acc[s][2] = pack2(x4, x5); acc[s][3] = pack2(x6, x7);
        sum[s] = ((x0 + x1) + (x2 + x3)) + ((x4 + x5) + (x6 + x7));
        ss[s]  = ((x0*x0 + x1*x1) + (x2*x2 + x3*x3)) + ((x4*x4 + x5*x5) + (x6*x6 + x7*x7));
    }
    #pragma unroll
    for (int s = 0; s < 8; ++s) {
        #pragma unroll
        for (int off = 16; off > 0; off >>= 1) {
            sum[s] += __shfl_xor_sync(0xffffffffu, sum[s], off);
            ss[s]  += __shfl_xor_sync(0xffffffffu, ss[s],  off);
        }
    }

    const int warp = t >> 5, lane = t & 31;
    __syncthreads();                 // all smem M reads done; safe to reuse buf0
    if (lane == 0) {
        #pragma unroll
        for (int s = 0; s < 8; ++s) {
            red[(warp * 8 + s) * 2 + 0] = sum[s];
            red[(warp * 8 + s) * 2 + 1] = ss[s];
        }
    }
    __syncthreads();

    const int wp = tg * 2;
    const float4 g0 = *(const float4*)(gamma + o0), g1 = *(const float4*)(gamma + o1);
    const float4 e0 = *(const float4*)(beta  + o0), e1 = *(const float4*)(beta  + o1);
    float* orow_base = out + ((size_t)bb * S_ + s0 + tg * 8) * D_;

    #pragma unroll
    for (int s = 0; s < 8; ++s) {
        float fs  = red[(wp * 8 + s) * 2 + 0] + red[((wp + 1) * 8 + s) * 2 + 0];
        float fss = red[(wp * 8 + s) * 2 + 1] + red[((wp + 1) * 8 + s) * 2 + 1];
        float mean = fs * (1.0f / 512.0f);
        float var  = fss * (1.0f / 512.0f) - mean * mean;
        float rstd = rsqrtf(var + 1e-5f);
        float2 p0 = unpack2(acc[s][0]), p1 = unpack2(acc[s][1]);
        float2 p2 = unpack2(acc[s][2]), p3 = unpack2(acc[s][3]);
        float4 r0, r1;
        r0.x = (p0.x - mean) * rstd * g0.x + e0.x;
        r0.y = (p0.y - mean) * rstd * g0.y + e0.y;
        r0.z = (p1.x - mean) * rstd * g0.z + e0.z;
        r0.w = (p1.y - mean) * rstd * g0.w + e0.w;
        r1.x = (p2.x - mean) * rstd * g1.x + e1.x;
        r1.y = (p2.y - mean) * rstd * g1.y + e1.y;
        r1.z = (p3.x - mean) * rstd * g1.z + e1.z;
        r1.w = (p3.y - mean) * rstd * g1.w + e1.w;
        *(float4*)(orow_base + s * D_ + o0) = r0;
        *(float4*)(orow_base + s * D_ + o1) = r1;
    }
}

// ---------------------------------------------------------------------------
// launch
// ---------------------------------------------------------------------------
extern "C" void kernel_launch(void* const* d_in, const int* in_sizes, int n_in,
                              void* d_out, int out_size) {
    const int*   seq   = (const int*)  d_in[0];
    const int*   kid   = (const int*)  d_in[1];
    const float* emb   = (const float*)d_in[2];
    const float* kt    = (const float*)d_in[3];
    const float* W     = (const float*)d_in[4];
    const float* bias  = (const float*)d_in[5];
    const float* gamma = (const float*)d_in[6];
    const float* beta  = (const float*)d_in[7];
    float* out = (float*)d_out;

    k_proj<<<256, 256>>>(W, kt, kid);

    dim3 g2(S_ / TS, B_);   // (16, 8)
    k_main<<<g2, 256>>>(seq, kid, emb, bias, gamma, beta, out);
}

// round 3
// speedup vs baseline: 1.1815x; 1.1815x over previous
#include <cuda_runtime.h>
#include <cuda_bf16.h>
#include <cstdint>

#define B_   8
#define S_   512
#define D_   512
#define E_   128
#define VOC  32000
#define TS   16
#define KC   8
#define NCH  (E_ / KC)   // 16 chunks of 8 k-values

typedef unsigned long long u64;

// scratch: mT[b][i][o]  (2 MB), fully overwritten each call
__device__ float g_m[(size_t)B_ * E_ * D_];

// ---------------------------------------------------------------------------
// helpers
// ---------------------------------------------------------------------------
__device__ __forceinline__ void ffma2(u64 &d, u64 a, u64 b) {
    asm("fma.rn.f32x2 %0, %1, %2, %0;" : "+l"(d) : "l"(a), "l"(b));
}
__device__ __forceinline__ u64 pack2(float x, float y) {
    u64 r; asm("mov.b64 %0, {%1, %2};" : "=l"(r) : "f"(x), "f"(y)); return r;
}
__device__ __forceinline__ float2 unpack2(u64 v) {
    float2 f; asm("mov.b64 {%0, %1}, %2;" : "=f"(f.x), "=f"(f.y) : "l"(v)); return f;
}
__device__ __forceinline__ void cp16(void* s, const void* g) {
    unsigned sa = (unsigned)__cvta_generic_to_shared(s);
    asm volatile("cp.async.cg.shared.global [%0], [%1], 16;" :: "r"(sa), "l"(g));
}
__device__ __forceinline__ void cp_commit() { asm volatile("cp.async.commit_group;"); }
template<int N> __device__ __forceinline__ void cp_wait() {
    asm volatile("cp.async.wait_group %0;" :: "n"(N));
}

// ---------------------------------------------------------------------------
// Kernel 1: mT[b][i][o] = sum_j W[o][i][j] * king_table[king_id[b]][j]
// Block tile: 8 o x 32 i (256 rows of W, 128KB). W streamed through smem via
// cp.async in 4 j-chunks of 32 (32KB each) -> fully-coalesced 128B lines.
// One thread per row; smem reads XOR-swizzled (conflict-free per 8-lane
// LDS.128 phase). Results staged in padded smem, stored coalesced.
// grid = (64 o-tiles, 4 i-chunks) = 256 blocks.
// ---------------------------------------------------------------------------
__global__ __launch_bounds__(256) void k_proj(const float* __restrict__ W,
                                              const float* __restrict__ kt,
                                              const int*   __restrict__ kid) {
    __shared__ __align__(16) float sk[B_][E_];        // 4 KB
    __shared__ __align__(16) float sW[256 * 32];      // 32 KB: [row][8 float4 swizzled]
    __shared__ float sres[B_ * 32 * 9];               // 9 KB padded transpose

    const int t = threadIdx.x;
    const int o_base = blockIdx.x * 8;
    const int i0     = blockIdx.y * 32;

    for (int idx = t; idx < B_ * E_; idx += 256) {
        int b = idx >> 7, j = idx & 127;
        sk[b][j] = kt[(size_t)kid[b] * E_ + j];
    }
    __syncthreads();

    // this thread's W row: o = t>>5, i = t&31
    const int ro = t >> 5, ri = t & 31;
    const float* Wrow = W + ((size_t)(o_base + ro) * E_ + (i0 + ri)) * E_;
    const int myperm = t & 7;

    u64 acc[B_];
    #pragma unroll
    for (int b = 0; b < B_; ++b) acc[b] = 0ull;

    for (int jc = 0; jc < 4; ++jc) {
        // load 32KB chunk: 2048 float4s, 8 per thread
        #pragma unroll
        for (int v = 0; v < 8; ++v) {
            int flat = v * 256 + t;          // [0,2048)
            int row = flat >> 3, j4 = flat & 7;
            int perm = j4 ^ (row & 7);
            const float* src = W + ((size_t)(o_base + (row >> 5)) * E_ + (i0 + (row & 31))) * E_
                                 + jc * 32 + j4 * 4;
            cp16(&sW[(row * 8 + perm) * 4], src);
        }
        cp_commit();
        cp_wait<0>();
        __syncthreads();

        #pragma unroll
        for (int j4 = 0; j4 < 8; ++j4) {
            ulonglong2 w = *(const ulonglong2*)(&sW[(t * 8 + (j4 ^ myperm)) * 4]);
            #pragma unroll
            for (int b = 0; b < B_; ++b) {
                ulonglong2 kv = *(const ulonglong2*)(&sk[b][jc * 32 + j4 * 4]);
                ffma2(acc[b], w.x, kv.x);
                ffma2(acc[b], w.y, kv.y);
            }
        }
        __syncthreads();
    }

    // transpose via padded smem, then coalesced store
    #pragma unroll
    for (int b = 0; b < B_; ++b) {
        float2 f = unpack2(acc[b]);
        sres[b * 288 + ri * 9 + ro] = f.x + f.y;
    }
    __syncthreads();
    #pragma unroll
    for (int v = 0; v < 8; ++v) {
        int idx = v * 256 + t;               // [0,2048)
        int b = idx >> 8, r = idx & 255;
        int i = r >> 3, o = r & 7;
        g_m[((size_t)b << 16) + ((size_t)(i0 + i) << 9) + o_base + o] =
            sres[b * 288 + i * 9 + o];
    }
}

// ---------------------------------------------------------------------------
// Kernel 2: per (b, 16-seq tile): gather A = emb rows (16x128) into smem,
// x = A * mT[b] (128x512), cp.async double-buffered M chunks, fused bias + LN.
// 128 threads, 4 CTAs/SM. Microtile 8s x 8o per thread.
// ---------------------------------------------------------------------------
__global__ __launch_bounds__(128, 4) void k_main(const int*   __restrict__ seq,
                                                 const int*   __restrict__ kid,
                                                 const float* __restrict__ emb,
                                                 const float* __restrict__ bias,
                                                 const float* __restrict__ gamma,
                                                 const float* __restrict__ beta,
                                                 float*       __restrict__ out) {
    __shared__ __align__(16) unsigned char smem[40960];
    float* sA  = (float*)smem;                 // A[16][128]  (8 KB)
    float* sM0 = (float*)(smem + 8192);        // M chunk buf0 (16 KB)
    float* sM1 = (float*)(smem + 24576);       // M chunk buf1 (16 KB)
    float* red = (float*)(smem + 8192);        // LN reduction, reuses buf0

    const int t  = threadIdx.x;
    const int bb = blockIdx.y;
    const int s0 = blockIdx.x * TS;
    const int king = kid[bb];
    const float* Mg = g_m + ((size_t)bb << 16);   // mT[b] : [128][512]

    {
        const float* embk = emb + (size_t)king * VOC * E_;
        #pragma unroll
        for (int v = 0; v < 4; ++v) {
            int idx = t + v * 128;            // float4 index in [0,512)
            int row = idx >> 5, c4 = idx & 31;
            int tok = seq[bb * S_ + s0 + row];
            cp16(sA + idx * 4, embk + (size_t)tok * E_ + c4 * 4);
        }
        #pragma unroll
        for (int v = 0; v < 8; ++v) {
            int idx = t + v * 128;
            cp16(sM0 + idx * 4, Mg + idx * 4);
        }
        cp_commit();
        #pragma unroll
        for (int v = 0; v < 8; ++v) {
            int idx = t + v * 128;
            cp16(sM1 + idx * 4, Mg + KC * D_ + idx * 4);
        }
        cp_commit();
    }

    const int tq = t & 63, tg = t >> 6;
    const int o0 = tq * 4, o1 = o0 + 256;

    u64 acc[8][4];
    #pragma unroll
    for (int s = 0; s < 8; ++s) {
        acc[s][0] = 0ull; acc[s][1] = 0ull; acc[s][2] = 0ull; acc[s][3] = 0ull;
    }

    const float* Arow = sA + tg * 8 * E_;

    #pragma unroll 1
    for (int c = 0; c < NCH; ++c) {
        if (c < NCH - 1) cp_wait<1>(); else cp_wait<0>();
        __syncthreads();
        const float* Mb = (c & 1) ? sM1 : sM0;
        #pragma unroll
        for (int k4 = 0; k4 < 2; ++k4) {
            float4 av[8];
            #pragma unroll
            for (int s = 0; s < 8; ++s)
                av[s] = *(const float4*)(Arow + s * E_ + c * KC + k4 * 4);
            #pragma unroll
            for (int kk = 0; kk < 4; ++kk) {
                const float* mrow = Mb + (k4 * 4 + kk) * D_;
                ulonglong2 m0 = *(const ulonglong2*)(mrow + o0);
                ulonglong2 m1 = *(const ulonglong2*)(mrow + o1);
                #pragma unroll
                for (int s = 0; s < 8; ++s) {
                    float a = (kk == 0) ? av[s].x : (kk == 1) ? av[s].y
                            : (kk == 2) ? av[s].z : av[s].w;
                    u64 aa = pack2(a, a);
                    ffma2(acc[s][0], aa, m0.x);
                    ffma2(acc[s][1], aa, m0.y);
                    ffma2(acc[s][2], aa, m1.x);
                    ffma2(acc[s][3], aa, m1.y);
                }
            }
        }
        __syncthreads();
        if (c + 2 < NCH) {
            float* dst = (c & 1) ? sM1 : sM0;
            const float* src = Mg + (size_t)(c + 2) * KC * D_;
            #pragma unroll
            for (int v = 0; v < 8; ++v) {
                int idx = t + v * 128;
                cp16(dst + idx * 4, src + idx * 4);
            }
            cp_commit();
        }
    }

    // ---- epilogue: bias + LN stats ----
    const float4 b0 = *(const float4*)(bias + o0);
    const float4 b1 = *(const float4*)(bias + o1);
    float sum[8], ss[8];
    #pragma unroll
    for (int s = 0; s < 8; ++s) {
        float2 p0 = unpack2(acc[s][0]), p1 = unpack2(acc[s][1]);
        float2 p2 = unpack2(acc[s][2]), p3 = unpack2(acc[s][3]);
        float x0 = p0.x + b0.x, x1 = p0.y + b0.y, x2 = p1.x + b0.z, x3 = p1.y + b0.w;
        float x4 = p2.x + b1.x, x5 = p2.y + b1.y, x6 = p3.x + b1.z, x7 = p3.y + b1.w;
        acc[s][0] = pack2(x0, x1); acc[s][1] = pack2(x2, x3);
        acc[s][2] = pack2(x4, x5); acc[s][3] = pack2(x6, x7);
        sum[s] = ((x0 + x1) + (x2 + x3)) + ((x4 + x5) + (x6 + x7));
        ss[s]  = ((x0*x0 + x1*x1) + (x2*x2 + x3*x3)) + ((x4*x4 + x5*x5) + (x6*x6 + x7*x7));
    }
    #pragma unroll
    for (int s = 0; s < 8; ++s) {
        #pragma unroll
        for (int off = 16; off > 0; off >>= 1) {
            sum[s] += __shfl_xor_sync(0xffffffffu, sum[s], off);
            ss[s]  += __shfl_xor_sync(0xffffffffu, ss[s],  off);
        }
    }

    const int warp = t >> 5, lane = t & 31;
    __syncthreads();
    if (lane == 0) {
        #pragma unroll
        for (int s = 0; s < 8; ++s) {
            red[(warp * 8 + s) * 2 + 0] = sum[s];
            red[(warp * 8 + s) * 2 + 1] = ss[s];
        }
    }
    __syncthreads();

    const int wp = tg * 2;
    const float4 g0 = *(const float4*)(gamma + o0), g1 = *(const float4*)(gamma + o1);
    const float4 e0 = *(const float4*)(beta  + o0), e1 = *(const float4*)(beta  + o1);
    float* orow_base = out + ((size_t)bb * S_ + s0 + tg * 8) * D_;

    #pragma unroll
    for (int s = 0; s < 8; ++s) {
        float fs  = red[(wp * 8 + s) * 2 + 0] + red[((wp + 1) * 8 + s) * 2 + 0];
        float fss = red[(wp * 8 + s) * 2 + 1] + red[((wp + 1) * 8 + s) * 2 + 1];
        float mean = fs * (1.0f / 512.0f);
        float var  = fss * (1.0f / 512.0f) - mean * mean;
        float rstd = rsqrtf(var + 1e-5f);
        float2 p0 = unpack2(acc[s][0]), p1 = unpack2(acc[s][1]);
        float2 p2 = unpack2(acc[s][2]), p3 = unpack2(acc[s][3]);
        float4 r0, r1;
        r0.x = (p0.x - mean) * rstd * g0.x + e0.x;
        r0.y = (p0.y - mean) * rstd * g0.y + e0.y;
        r0.z = (p1.x - mean) * rstd * g0.z + e0.z;
        r0.w = (p1.y - mean) * rstd * g0.w + e0.w;
        r1.x = (p2.x - mean) * rstd * g1.x + e1.x;
        r1.y = (p2.y - mean) * rstd * g1.y + e1.y;
        r1.z = (p3.x - mean) * rstd * g1.z + e1.z;
        r1.w = (p3.y - mean) * rstd * g1.w + e1.w;
        *(float4*)(orow_base + s * D_ + o0) = r0;
        *(float4*)(orow_base + s * D_ + o1) = r1;
    }
}

// ---------------------------------------------------------------------------
// launch
// ---------------------------------------------------------------------------
extern "C" void kernel_launch(void* const* d_in, const int* in_sizes, int n_in,
                              void* d_out, int out_size) {
    const int*   seq   = (const int*)  d_in[0];
    const int*   kid   = (const int*)  d_in[1];
    const float* emb   = (const float*)d_in[2];
    const float* kt    = (const float*)d_in[3];
    const float* W     = (const float*)d_in[4];
    const float* bias  = (const float*)d_in[5];
    const float* gamma = (const float*)d_in[6];
    const float* beta  = (const float*)d_in[7];
    float* out = (float*)d_out;

    dim3 g1(64, 4);     // 8-o tiles x 32-i chunks
    k_proj<<<g1, 256>>>(W, kt, kid);

    dim3 g2(S_ / TS, B_);   // (32, 8)
    k_main<<<g2, 128>>>(seq, kid, emb, bias, gamma, beta, out);
}